// round 1
// baseline (speedup 1.0000x reference)
#include <cuda_runtime.h>
#include <cuda_bf16.h>
#include <cstdint>

#define Hh 100
#define HP 128
#define Bb 64
#define Ss 384
#define Ll 2
#define EPSV 1e-6f
#define NEG_INF (-3.402823466e38f)

typedef unsigned long long ull;

// ---------------- packed f32x2 helpers (Blackwell) ----------------
__device__ __forceinline__ ull pk(float x, float y) {
    ull r; asm("mov.b64 %0, {%1,%2};" : "=l"(r) : "f"(x), "f"(y)); return r;
}
__device__ __forceinline__ void upk(ull v, float& x, float& y) {
    asm("mov.b64 {%0,%1}, %2;" : "=f"(x), "=f"(y) : "l"(v));
}
__device__ __forceinline__ ull mul2(ull a, ull b) {
    ull d; asm("mul.rn.f32x2 %0, %1, %2;" : "=l"(d) : "l"(a), "l"(b)); return d;
}
__device__ __forceinline__ ull add2(ull a, ull b) {
    ull d; asm("add.rn.f32x2 %0, %1, %2;" : "=l"(d) : "l"(a), "l"(b)); return d;
}
__device__ __forceinline__ ull fma2(ull a, ull b, ull c) {
    ull d; asm("fma.rn.f32x2 %0, %1, %2, %3;" : "=l"(d) : "l"(a), "l"(b), "l"(c)); return d;
}

// ---------------- scratch (device globals; no allocs allowed) ----------------
__device__ float g_pT[2][Bb * Ss * HP];     // [dir][(b*S+i)*HP + h]
__device__ float g_qT[2][Bb * Ss * HP];
__device__ float g_att[2][Bb * Ss * Ss];    // [dir][(b*S+i)*S + j]

__device__ float g_inv_np [2][Bb * Ss];
__device__ float g_inv_nq [2][Bb * Ss];
__device__ float g_inv_w1p[2][2][Bb * Ss];
__device__ float g_inv_w2p[2][2][Bb * Ss];
__device__ float g_inv_w3p[2][2][Bb * Ss];
__device__ float g_inv_w4p[2][2][Bb * Ss];
__device__ float g_inv_w2q[2][2][Bb * Ss];
__device__ float g_inv_w4q[2][2][Bb * Ss];
__device__ float g_inv_w1ql[2][2][Bb];
__device__ float g_rowinv[2][Bb * Ss];
__device__ int   g_idx   [2][Bb * Ss];

__device__ __forceinline__ float invclamp(float s) {
    return 1.0f / fmaxf(sqrtf(s), EPSV);
}
__device__ __forceinline__ float wred(float v) {
    #pragma unroll
    for (int off = 16; off >= 1; off >>= 1) v += __shfl_xor_sync(0xffffffffu, v, off);
    return v;
}

// ---------------- 1) transpose (H,B,S) -> (b,col,HP) with zero pad ----------------
__global__ __launch_bounds__(256) void k_transpose(
    const float* __restrict__ p_f, const float* __restrict__ p_b,
    const float* __restrict__ q_f, const float* __restrict__ q_b)
{
    const int z = blockIdx.z;
    const float* src = (z == 0) ? p_f : (z == 1) ? p_b : (z == 2) ? q_f : q_b;
    float* dst = (z == 0) ? g_pT[0] : (z == 1) ? g_pT[1] : (z == 2) ? g_qT[0] : g_qT[1];
    const int b = blockIdx.y;
    const int i0 = blockIdx.x * 64;
    __shared__ float sm[Hh][65];

    for (int e = threadIdx.x; e < Hh * 64; e += 256) {
        int h = e / 64, i = e % 64;
        sm[h][i] = src[(h * Bb + b) * Ss + i0 + i];
    }
    __syncthreads();
    for (int e = threadIdx.x; e < 64 * HP; e += 256) {
        int i = e / HP, h = e % HP;
        dst[(b * Ss + i0 + i) * HP + h] = (h < Hh) ? sm[h][i] : 0.0f;
    }
}

// ---------------- 2) per-column clamped inverse norms ----------------
__global__ __launch_bounds__(256) void k_norms(
    const float* __restrict__ w1f, const float* __restrict__ w1b,
    const float* __restrict__ w2f, const float* __restrict__ w2b,
    const float* __restrict__ w3f, const float* __restrict__ w4f)
{
    const int kind = blockIdx.z;  // 0 = p, 1 = q
    const int d = blockIdx.y;
    const int c = blockIdx.x * 8 + (threadIdx.x >> 5);
    const int lane = threadIdx.x & 31;
    const float* base = (kind ? g_qT[d] : g_pT[d]) + c * HP;
    const float* wa1 = d ? w1b : w1f;
    const float* wa2 = d ? w2b : w2f;
    const float* wa3 = w3f;  // reference uses w3f for BOTH directions
    const float* wa4 = w4f;  // reference uses w4f for BOTH directions

    float s0 = 0.f, s1[2] = {0.f, 0.f}, s2[2] = {0.f, 0.f}, s3[2] = {0.f, 0.f}, s4[2] = {0.f, 0.f};
    for (int h = lane; h < Hh; h += 32) {
        float v = base[h], v2 = v * v;
        s0 += v2;
        #pragma unroll
        for (int l = 0; l < 2; ++l) {
            float a;
            a = wa1[l * Hh + h]; s1[l] += a * a * v2;
            a = wa2[l * Hh + h]; s2[l] += a * a * v2;
            a = wa3[l * Hh + h]; s3[l] += a * a * v2;
            a = wa4[l * Hh + h]; s4[l] += a * a * v2;
        }
    }
    s0 = wred(s0);
    #pragma unroll
    for (int l = 0; l < 2; ++l) {
        s1[l] = wred(s1[l]); s2[l] = wred(s2[l]); s3[l] = wred(s3[l]); s4[l] = wred(s4[l]);
    }
    if (lane == 0) {
        if (kind == 0) {
            g_inv_np[d][c] = invclamp(s0);
            #pragma unroll
            for (int l = 0; l < 2; ++l) {
                g_inv_w1p[d][l][c] = invclamp(s1[l]);
                g_inv_w2p[d][l][c] = invclamp(s2[l]);
                g_inv_w3p[d][l][c] = invclamp(s3[l]);
                g_inv_w4p[d][l][c] = invclamp(s4[l]);
            }
        } else {
            g_inv_nq[d][c] = invclamp(s0);
            #pragma unroll
            for (int l = 0; l < 2; ++l) {
                g_inv_w2q[d][l][c] = invclamp(s2[l]);
                g_inv_w4q[d][l][c] = invclamp(s4[l]);
            }
            if ((c % Ss) == Ss - 1) {
                #pragma unroll
                for (int l = 0; l < 2; ++l) g_inv_w1ql[d][l][c / Ss] = invclamp(s1[l]);
            }
        }
    }
}

// ---------------- 3) fused cross kernel: att + m2 + rowsum + argmax ----------------
__global__ __launch_bounds__(256) void k_cross(
    const float* __restrict__ w2f, const float* __restrict__ w2b,
    float* __restrict__ out)
{
    const int d = blockIdx.z, b = blockIdx.y, i0 = blockIdx.x * 64;
    const int tid = threadIdx.x, tx = tid & 15, ty = tid >> 4;

    __shared__ __align__(16) float As[Hh][64];
    __shared__ __align__(16) float Bs[50][64];
    __shared__ ull ws0[104], ws1[104];

    const float* wa2 = d ? w2b : w2f;
    if (tid < Hh) {
        float a = wa2[tid];       ws0[tid] = pk(a * a, a * a);
        float c = wa2[Hh + tid];  ws1[tid] = pk(c * c, c * c);
    }
    // load A tile [100 h][64 i] (conflict-free STS; strided L2 reads, once/block)
    {
        const float* src = &g_pT[d][(b * Ss + i0) * HP];
        int i = tid & 63, h2 = tid >> 6;
        #pragma unroll
        for (int r = 0; r < 25; ++r) {
            int h = r * 4 + h2;
            As[h][i] = src[i * HP + h];
        }
    }

    float inp[4], iw2p0[4], iw2p1[4];
    #pragma unroll
    for (int ii = 0; ii < 4; ++ii) {
        int ci = b * Ss + i0 + ty * 4 + ii;
        inp[ii]   = g_inv_np[d][ci];
        iw2p0[ii] = g_inv_w2p[d][0][ci];
        iw2p1[ii] = g_inv_w2p[d][1][ci];
    }
    float rsum[4] = {0.f, 0.f, 0.f, 0.f};
    float rmax[4] = {NEG_INF, NEG_INF, NEG_INF, NEG_INF};
    int   rarg[4] = {0, 0, 0, 0};
    float m2m[2][4] = {{NEG_INF, NEG_INF, NEG_INF, NEG_INF}, {NEG_INF, NEG_INF, NEG_INF, NEG_INF}};

    for (int j0 = 0; j0 < Ss; j0 += 64) {
        ull acc0[4][2], acca[4][2], accb[4][2];
        #pragma unroll
        for (int ii = 0; ii < 4; ++ii)
            acc0[ii][0] = acc0[ii][1] = acca[ii][0] = acca[ii][1] = accb[ii][0] = accb[ii][1] = 0ull;

        for (int hb = 0; hb < Hh; hb += 50) {
            __syncthreads();
            {   // load B chunk [50 h][64 j]
                const float* srcq = &g_qT[d][(b * Ss + j0) * HP + hb];
                int j = tid & 63, h2 = tid >> 6;
                #pragma unroll
                for (int r = 0; r < 13; ++r) {
                    int h = r * 4 + h2;
                    if (h < 50) Bs[h][j] = srcq[j * HP + h];
                }
            }
            __syncthreads();
            #pragma unroll 5
            for (int h = 0; h < 50; ++h) {
                float4 av = *(const float4*)&As[hb + h][ty * 4];
                float4 bv = *(const float4*)&Bs[h][tx * 4];
                ull w0 = ws0[hb + h], w1 = ws1[hb + h];
                ull b01 = pk(bv.x, bv.y), b23 = pk(bv.z, bv.w);
                float aa[4] = {av.x, av.y, av.z, av.w};
                #pragma unroll
                for (int ii = 0; ii < 4; ++ii) {
                    ull ap = pk(aa[ii], aa[ii]);
                    ull t0 = mul2(ap, b01);
                    ull t1 = mul2(ap, b23);
                    acc0[ii][0] = add2(acc0[ii][0], t0);
                    acc0[ii][1] = add2(acc0[ii][1], t1);
                    acca[ii][0] = fma2(w0, t0, acca[ii][0]);
                    acca[ii][1] = fma2(w0, t1, acca[ii][1]);
                    accb[ii][0] = fma2(w1, t0, accb[ii][0]);
                    accb[ii][1] = fma2(w1, t1, accb[ii][1]);
                }
            }
        }
        // epilogue for this j-tile
        float inq[4], iq20[4], iq21[4];
        #pragma unroll
        for (int jj = 0; jj < 4; ++jj) {
            int cj = b * Ss + j0 + tx * 4 + jj;
            inq[jj]  = g_inv_nq[d][cj];
            iq20[jj] = g_inv_w2q[d][0][cj];
            iq21[jj] = g_inv_w2q[d][1][cj];
        }
        #pragma unroll
        for (int ii = 0; ii < 4; ++ii) {
            float d0[4], da[4], db[4];
            upk(acc0[ii][0], d0[0], d0[1]); upk(acc0[ii][1], d0[2], d0[3]);
            upk(acca[ii][0], da[0], da[1]); upk(acca[ii][1], da[2], da[3]);
            upk(accb[ii][0], db[0], db[1]); upk(accb[ii][1], db[2], db[3]);
            float attv[4];
            #pragma unroll
            for (int jj = 0; jj < 4; ++jj) attv[jj] = d0[jj] * inp[ii] * inq[jj];
            float* attp = &g_att[d][(b * Ss + i0 + ty * 4 + ii) * Ss + j0 + tx * 4];
            *(float4*)attp = make_float4(attv[0], attv[1], attv[2], attv[3]);
            #pragma unroll
            for (int jj = 0; jj < 4; ++jj) {
                rsum[ii] += attv[jj];
                if (attv[jj] > rmax[ii]) { rmax[ii] = attv[jj]; rarg[ii] = j0 + tx * 4 + jj; }
                m2m[0][ii] = fmaxf(m2m[0][ii], da[jj] * iw2p0[ii] * iq20[jj]);
                m2m[1][ii] = fmaxf(m2m[1][ii], db[jj] * iw2p1[ii] * iq21[jj]);
            }
        }
    }
    // cross-thread (tx-group of 16, same warp half) reductions
    #pragma unroll
    for (int ii = 0; ii < 4; ++ii) {
        float s = rsum[ii], mx = rmax[ii];
        int ag = rarg[ii];
        float m0 = m2m[0][ii], m1v = m2m[1][ii];
        #pragma unroll
        for (int off = 8; off >= 1; off >>= 1) {
            s += __shfl_xor_sync(0xffffffffu, s, off, 16);
            float omx = __shfl_xor_sync(0xffffffffu, mx, off, 16);
            int   oag = __shfl_xor_sync(0xffffffffu, ag, off, 16);
            if (omx > mx || (omx == mx && oag < ag)) { mx = omx; ag = oag; }
            m0  = fmaxf(m0,  __shfl_xor_sync(0xffffffffu, m0,  off, 16));
            m1v = fmaxf(m1v, __shfl_xor_sync(0xffffffffu, m1v, off, 16));
        }
        if (tx == 0) {
            int i = i0 + ty * 4 + ii;
            int ci = b * Ss + i;
            g_rowinv[d][ci] = 1.0f / s;
            g_idx[d][ci] = ag;
            out[(((2 + d) * Ss + i) * Bb + b) * Ll + 0] = m0;
            out[(((2 + d) * Ss + i) * Bb + b) * Ll + 1] = m1v;
        }
    }
}

// ---------------- 4) hmean GEMM fused with m3 epilogue ----------------
__global__ __launch_bounds__(256) void k_hmean(
    const float* __restrict__ w3f, float* __restrict__ out)
{
    const int d = blockIdx.z, b = blockIdx.y, i0 = blockIdx.x * 64;
    const int tid = threadIdx.x, tx = tid & 15, ty = tid >> 4;

    __shared__ float Ats[32][65];
    __shared__ ull   Qs2[32][64];
    __shared__ float ws3[2][HP];

    if (tid < HP) {
        float a = (tid < Hh) ? w3f[tid] : 0.0f;
        float c = (tid < Hh) ? w3f[Hh + tid] : 0.0f;
        ws3[0][tid] = a * a;
        ws3[1][tid] = c * c;
    }

    ull hm[4][4];
    #pragma unroll
    for (int ii = 0; ii < 4; ++ii)
        #pragma unroll
        for (int k = 0; k < 4; ++k) hm[ii][k] = 0ull;

    const int h0 = tx * 8;

    for (int j0 = 0; j0 < Ss; j0 += 32) {
        __syncthreads();
        {   // att tile transposed [j][i] (coalesced reads over j)
            int j = tid & 31, i2 = tid >> 5;
            #pragma unroll
            for (int r = 0; r < 8; ++r) {
                int i = r * 8 + i2;
                Ats[j][i] = g_att[d][(b * Ss + i0 + i) * Ss + j0 + j];
            }
        }
        {   // q tile as packed pairs [j][hp]
            const ull* srcq = (const ull*)&g_qT[d][(b * Ss + j0) * HP];
            #pragma unroll
            for (int r = 0; r < 8; ++r) {
                int e = r * 256 + tid;
                int j = e >> 6, hp = e & 63;
                Qs2[j][hp] = srcq[j * (HP / 2) + hp];
            }
        }
        __syncthreads();
        #pragma unroll 4
        for (int j = 0; j < 32; ++j) {
            float a0 = Ats[j][ty * 4 + 0], a1 = Ats[j][ty * 4 + 1];
            float a2 = Ats[j][ty * 4 + 2], a3 = Ats[j][ty * 4 + 3];
            ull q0 = Qs2[j][(h0 >> 1) + 0], q1 = Qs2[j][(h0 >> 1) + 1];
            ull q2 = Qs2[j][(h0 >> 1) + 2], q3 = Qs2[j][(h0 >> 1) + 3];
            ull ap;
            ap = pk(a0, a0);
            hm[0][0] = fma2(ap, q0, hm[0][0]); hm[0][1] = fma2(ap, q1, hm[0][1]);
            hm[0][2] = fma2(ap, q2, hm[0][2]); hm[0][3] = fma2(ap, q3, hm[0][3]);
            ap = pk(a1, a1);
            hm[1][0] = fma2(ap, q0, hm[1][0]); hm[1][1] = fma2(ap, q1, hm[1][1]);
            hm[1][2] = fma2(ap, q2, hm[1][2]); hm[1][3] = fma2(ap, q3, hm[1][3]);
            ap = pk(a2, a2);
            hm[2][0] = fma2(ap, q0, hm[2][0]); hm[2][1] = fma2(ap, q1, hm[2][1]);
            hm[2][2] = fma2(ap, q2, hm[2][2]); hm[2][3] = fma2(ap, q3, hm[2][3]);
            ap = pk(a3, a3);
            hm[3][0] = fma2(ap, q0, hm[3][0]); hm[3][1] = fma2(ap, q1, hm[3][1]);
            hm[3][2] = fma2(ap, q2, hm[3][2]); hm[3][3] = fma2(ap, q3, hm[3][3]);
        }
    }

    // m3 epilogue: per-i reductions of w3^2 * p * hmean and w3^2 * hmean^2
    #pragma unroll
    for (int ii = 0; ii < 4; ++ii) {
        int i = i0 + ty * 4 + ii;
        int ci = b * Ss + i;
        const float* prow = &g_pT[d][ci * HP + h0];
        float s1a = 0.f, s1b = 0.f, s2a = 0.f, s2b = 0.f;
        #pragma unroll
        for (int k = 0; k < 4; ++k) {
            float hx, hy; upk(hm[ii][k], hx, hy);
            float px = prow[2 * k], py = prow[2 * k + 1];
            float w0x = ws3[0][h0 + 2 * k], w0y = ws3[0][h0 + 2 * k + 1];
            float w1x = ws3[1][h0 + 2 * k], w1y = ws3[1][h0 + 2 * k + 1];
            s1a += w0x * px * hx + w0y * py * hy;
            s2a += w0x * hx * hx + w0y * hy * hy;
            s1b += w1x * px * hx + w1y * py * hy;
            s2b += w1x * hx * hx + w1y * hy * hy;
        }
        #pragma unroll
        for (int off = 8; off >= 1; off >>= 1) {
            s1a += __shfl_xor_sync(0xffffffffu, s1a, off, 16);
            s2a += __shfl_xor_sync(0xffffffffu, s2a, off, 16);
            s1b += __shfl_xor_sync(0xffffffffu, s1b, off, 16);
            s2b += __shfl_xor_sync(0xffffffffu, s2b, off, 16);
        }
        if (tx == 0) {
            float r = g_rowinv[d][ci];
            float ar = fabsf(r);
            float m30 = (r * s1a) * g_inv_w3p[d][0][ci] / fmaxf(ar * sqrtf(s2a), EPSV);
            float m31 = (r * s1b) * g_inv_w3p[d][1][ci] / fmaxf(ar * sqrtf(s2b), EPSV);
            out[(((4 + d) * Ss + i) * Bb + b) * Ll + 0] = m30;
            out[(((4 + d) * Ss + i) * Bb + b) * Ll + 1] = m31;
        }
    }
}

// ---------------- 5) m1 (last column) and m4 (argmax column) ----------------
__global__ __launch_bounds__(256) void k_m14(
    const float* __restrict__ w1f, const float* __restrict__ w1b,
    const float* __restrict__ w4f, float* __restrict__ out)
{
    const int d = blockIdx.y;
    const int c = blockIdx.x * 8 + (threadIdx.x >> 5);
    const int lane = threadIdx.x & 31;
    const int b = c / Ss, i = c % Ss;
    const int jm = g_idx[d][c];

    const float* prow = g_pT[d] + c * HP;
    const float* ql = g_qT[d] + (b * Ss + Ss - 1) * HP;
    const float* qm = g_qT[d] + (b * Ss + jm) * HP;
    const float* wa1 = d ? w1b : w1f;

    float s1[2] = {0.f, 0.f}, s4[2] = {0.f, 0.f};
    for (int h = lane; h < Hh; h += 32) {
        float p = prow[h];
        float t1 = p * ql[h];
        float t4 = p * qm[h];
        #pragma unroll
        for (int l = 0; l < 2; ++l) {
            float a;
            a = wa1[l * Hh + h]; s1[l] += a * a * t1;
            a = w4f[l * Hh + h]; s4[l] += a * a * t4;
        }
    }
    #pragma unroll
    for (int l = 0; l < 2; ++l) { s1[l] = wred(s1[l]); s4[l] = wred(s4[l]); }
    if (lane == 0) {
        #pragma unroll
        for (int l = 0; l < 2; ++l) {
            out[(((0 + d) * Ss + i) * Bb + b) * Ll + l] =
                s1[l] * g_inv_w1p[d][l][c] * g_inv_w1ql[d][l][b];
            out[(((6 + d) * Ss + i) * Bb + b) * Ll + l] =
                s4[l] * g_inv_w4p[d][l][c] * g_inv_w4q[d][l][b * Ss + jm];
        }
    }
}

// ---------------- launch ----------------
extern "C" void kernel_launch(void* const* d_in, const int* in_sizes, int n_in,
                              void* d_out, int out_size) {
    const float* p_f = (const float*)d_in[0];
    const float* p_b = (const float*)d_in[1];
    const float* q_f = (const float*)d_in[2];
    const float* q_b = (const float*)d_in[3];
    const float* w1f = (const float*)d_in[4];
    const float* w1b = (const float*)d_in[5];
    const float* w2f = (const float*)d_in[6];
    const float* w2b = (const float*)d_in[7];
    const float* w3f = (const float*)d_in[8];
    // w3b (d_in[9]) intentionally unused: reference uses w3f/w4f for both directions
    const float* w4f = (const float*)d_in[10];
    float* out = (float*)d_out;

    k_transpose<<<dim3(Ss / 64, Bb, 4), 256>>>(p_f, p_b, q_f, q_b);
    k_norms<<<dim3((Bb * Ss) / 8, 2, 2), 256>>>(w1f, w1b, w2f, w2b, w3f, w4f);
    k_cross<<<dim3(Ss / 64, Bb, 2), 256>>>(w2f, w2b, out);
    k_hmean<<<dim3(Ss / 64, Bb, 2), 256>>>(w3f, out);
    k_m14<<<dim3((Bb * Ss) / 8, 2), 256>>>(w1f, w1b, w4f, out);
}

// round 2
// speedup vs baseline: 1.0316x; 1.0316x over previous
#include <cuda_runtime.h>
#include <cuda_bf16.h>
#include <cstdint>

#define Hh 100
#define HP 128
#define Bb 64
#define Ss 384
#define Ll 2
#define EPSV 1e-6f
#define NEG_INF (-3.402823466e38f)

typedef unsigned long long ull;

// ---------------- packed f32x2 helpers ----------------
__device__ __forceinline__ ull pk(float x, float y) {
    ull r; asm("mov.b64 %0, {%1,%2};" : "=l"(r) : "f"(x), "f"(y)); return r;
}
__device__ __forceinline__ void upk(ull v, float& x, float& y) {
    asm("mov.b64 {%0,%1}, %2;" : "=f"(x), "=f"(y) : "l"(v));
}
__device__ __forceinline__ ull fma2(ull a, ull b, ull c) {
    ull d; asm("fma.rn.f32x2 %0, %1, %2, %3;" : "=l"(d) : "l"(a), "l"(b), "l"(c)); return d;
}

// ---------------- scratch ----------------
__device__ float g_pT[2][Bb * Ss * HP];
__device__ float g_qT[2][Bb * Ss * HP];
__device__ float g_att[Bb * Ss * Ss];     // SINGLE direction at a time (L2-resident)

__device__ float g_inv_np [2][Bb * Ss];
__device__ float g_inv_nq [2][Bb * Ss];
__device__ float g_inv_w1p[2][2][Bb * Ss];
__device__ float g_inv_w2p[2][2][Bb * Ss];
__device__ float g_inv_w3p[2][2][Bb * Ss];
__device__ float g_inv_w4p[2][2][Bb * Ss];
__device__ float g_inv_w2q[2][2][Bb * Ss];
__device__ float g_inv_w4q[2][2][Bb * Ss];
__device__ float g_inv_w1ql[2][2][Bb];
__device__ float g_rowinv[2][Bb * Ss];
__device__ int   g_idx   [2][Bb * Ss];

__device__ __forceinline__ float invclamp(float s) {
    return 1.0f / fmaxf(sqrtf(s), EPSV);
}
__device__ __forceinline__ float wred(float v) {
    #pragma unroll
    for (int off = 16; off >= 1; off >>= 1) v += __shfl_xor_sync(0xffffffffu, v, off);
    return v;
}

// ---------------- 1) transpose ----------------
__global__ __launch_bounds__(256) void k_transpose(
    const float* __restrict__ p_f, const float* __restrict__ p_b,
    const float* __restrict__ q_f, const float* __restrict__ q_b)
{
    const int z = blockIdx.z;
    const float* src = (z == 0) ? p_f : (z == 1) ? p_b : (z == 2) ? q_f : q_b;
    float* dst = (z == 0) ? g_pT[0] : (z == 1) ? g_pT[1] : (z == 2) ? g_qT[0] : g_qT[1];
    const int b = blockIdx.y;
    const int i0 = blockIdx.x * 64;
    __shared__ float sm[Hh][65];

    for (int e = threadIdx.x; e < Hh * 64; e += 256) {
        int h = e / 64, i = e % 64;
        sm[h][i] = src[(h * Bb + b) * Ss + i0 + i];
    }
    __syncthreads();
    for (int e = threadIdx.x; e < 64 * (HP / 4); e += 256) {
        int i = e / (HP / 4), h4 = (e % (HP / 4)) * 4;
        float4 v;
        v.x = (h4 + 0 < Hh) ? sm[h4 + 0][i] : 0.0f;
        v.y = (h4 + 1 < Hh) ? sm[h4 + 1][i] : 0.0f;
        v.z = (h4 + 2 < Hh) ? sm[h4 + 2][i] : 0.0f;
        v.w = (h4 + 3 < Hh) ? sm[h4 + 3][i] : 0.0f;
        *(float4*)&dst[(b * Ss + i0 + i) * HP + h4] = v;
    }
}

// ---------------- 2) per-column clamped inverse norms ----------------
__global__ __launch_bounds__(256) void k_norms(
    const float* __restrict__ w1f, const float* __restrict__ w1b,
    const float* __restrict__ w2f, const float* __restrict__ w2b,
    const float* __restrict__ w3f, const float* __restrict__ w4f)
{
    const int kind = blockIdx.z;
    const int d = blockIdx.y;
    const int c = blockIdx.x * 8 + (threadIdx.x >> 5);
    const int lane = threadIdx.x & 31;
    const float* base = (kind ? g_qT[d] : g_pT[d]) + c * HP;
    const float* wa1 = d ? w1b : w1f;
    const float* wa2 = d ? w2b : w2f;
    const float* wa3 = w3f;  // reference uses w3f for BOTH directions
    const float* wa4 = w4f;  // reference uses w4f for BOTH directions

    float s0 = 0.f, s1[2] = {0.f, 0.f}, s2[2] = {0.f, 0.f}, s3[2] = {0.f, 0.f}, s4[2] = {0.f, 0.f};
    for (int h = lane; h < Hh; h += 32) {
        float v = base[h], v2 = v * v;
        s0 += v2;
        #pragma unroll
        for (int l = 0; l < 2; ++l) {
            float a;
            a = wa1[l * Hh + h]; s1[l] += a * a * v2;
            a = wa2[l * Hh + h]; s2[l] += a * a * v2;
            a = wa3[l * Hh + h]; s3[l] += a * a * v2;
            a = wa4[l * Hh + h]; s4[l] += a * a * v2;
        }
    }
    s0 = wred(s0);
    #pragma unroll
    for (int l = 0; l < 2; ++l) {
        s1[l] = wred(s1[l]); s2[l] = wred(s2[l]); s3[l] = wred(s3[l]); s4[l] = wred(s4[l]);
    }
    if (lane == 0) {
        if (kind == 0) {
            g_inv_np[d][c] = invclamp(s0);
            #pragma unroll
            for (int l = 0; l < 2; ++l) {
                g_inv_w1p[d][l][c] = invclamp(s1[l]);
                g_inv_w2p[d][l][c] = invclamp(s2[l]);
                g_inv_w3p[d][l][c] = invclamp(s3[l]);
                g_inv_w4p[d][l][c] = invclamp(s4[l]);
            }
        } else {
            g_inv_nq[d][c] = invclamp(s0);
            #pragma unroll
            for (int l = 0; l < 2; ++l) {
                g_inv_w2q[d][l][c] = invclamp(s2[l]);
                g_inv_w4q[d][l][c] = invclamp(s4[l]);
            }
            if ((c % Ss) == Ss - 1) {
                #pragma unroll
                for (int l = 0; l < 2; ++l) g_inv_w1ql[d][l][c / Ss] = invclamp(s1[l]);
            }
        }
    }
}

// ---------------- 3) cross: att + m2 + rowsum + argmax (one direction) ----------------
// dynamic smem layout (floats):
//   As0 [100][68]  @ 0       unweighted p tile (i consecutive)
//   Asa [100][68]  @ 6800    w2(l=0)^2-scaled p
//   Asb [100][68]  @ 13600   w2(l=1)^2-scaled p
//   Bs2 (ull) [50][4][16] @ 20400  pre-broadcast pk(q,q)
//   wsq [2][100]   @ 26800
#define CROSS_SMEM_FLOATS 27000
#define CROSS_SMEM_BYTES (CROSS_SMEM_FLOATS * 4)

__global__ __launch_bounds__(256, 2) void k_cross(
    const int d, const float* __restrict__ w2f, const float* __restrict__ w2b,
    float* __restrict__ out)
{
    extern __shared__ float smf[];
    float* As0 = smf;
    float* Asa = smf + 6800;
    float* Asb = smf + 13600;
    ull*   Bs2 = (ull*)(smf + 20400);
    float* wsq = smf + 26800;

    const int b = blockIdx.y, i0 = blockIdx.x * 64;
    const int tid = threadIdx.x, tx = tid & 15, ty = tid >> 4;
    const float* wa2 = d ? w2b : w2f;

    if (tid < Hh) {
        float a = wa2[tid];      wsq[tid] = a * a;
        float c = wa2[Hh + tid]; wsq[100 + tid] = c * c;
    }
    __syncthreads();

    // A prep: load p tile, build 3 scaled variants [h][i]
    {
        const float* srcA = &g_pT[d][(b * Ss + i0) * HP];
        for (int e = tid; e < 64 * 25; e += 256) {
            int i = e / 25, hc = e % 25;
            float4 v = *(const float4*)&srcA[i * HP + hc * 4];
            float vv[4] = {v.x, v.y, v.z, v.w};
            #pragma unroll
            for (int k = 0; k < 4; ++k) {
                int h = hc * 4 + k;
                As0[h * 68 + i] = vv[k];
                Asa[h * 68 + i] = vv[k] * wsq[h];
                Asb[h * 68 + i] = vv[k] * wsq[100 + h];
            }
        }
    }

    float inp[4], iw0[4], iw1[4];
    #pragma unroll
    for (int ii = 0; ii < 4; ++ii) {
        int ci = b * Ss + i0 + ty * 4 + ii;
        inp[ii] = g_inv_np[d][ci];
        iw0[ii] = g_inv_w2p[d][0][ci];
        iw1[ii] = g_inv_w2p[d][1][ci];
    }
    float rsum[4] = {0.f, 0.f, 0.f, 0.f};
    float rmax[4] = {NEG_INF, NEG_INF, NEG_INF, NEG_INF};
    int   rarg[4] = {0, 0, 0, 0};
    float m2m[2][4] = {{NEG_INF, NEG_INF, NEG_INF, NEG_INF}, {NEG_INF, NEG_INF, NEG_INF, NEG_INF}};

    for (int j0 = 0; j0 < Ss; j0 += 64) {
        ull acc[3][2][4];
        #pragma unroll
        for (int v = 0; v < 3; ++v)
            #pragma unroll
            for (int ih = 0; ih < 2; ++ih)
                #pragma unroll
                for (int jj = 0; jj < 4; ++jj) acc[v][ih][jj] = 0ull;

        for (int hb = 0; hb < Hh; hb += 50) {
            __syncthreads();
            {   // B chunk: pre-broadcast pk(q,q), interleaved [h][jj][slot]
                const float* srcB = &g_qT[d][(b * Ss + j0) * HP + hb];
                for (int e = tid; e < 64 * 25; e += 256) {
                    int j = e / 25, hc = e % 25;
                    float2 v = *(const float2*)&srcB[j * HP + hc * 2];
                    int jj = j & 3, js = j >> 2;
                    Bs2[((hc * 2 + 0) * 4 + jj) * 16 + js] = pk(v.x, v.x);
                    Bs2[((hc * 2 + 1) * 4 + jj) * 16 + js] = pk(v.y, v.y);
                }
            }
            __syncthreads();
            #pragma unroll 5
            for (int h = 0; h < 50; ++h) {
                int hg = hb + h;
                ulonglong2 a0 = *(const ulonglong2*)&As0[hg * 68 + ty * 4];
                ulonglong2 aa = *(const ulonglong2*)&Asa[hg * 68 + ty * 4];
                ulonglong2 ab = *(const ulonglong2*)&Asb[hg * 68 + ty * 4];
                #pragma unroll
                for (int jj = 0; jj < 4; ++jj) {
                    ull bb = Bs2[(h * 4 + jj) * 16 + tx];
                    acc[0][0][jj] = fma2(a0.x, bb, acc[0][0][jj]);
                    acc[0][1][jj] = fma2(a0.y, bb, acc[0][1][jj]);
                    acc[1][0][jj] = fma2(aa.x, bb, acc[1][0][jj]);
                    acc[1][1][jj] = fma2(aa.y, bb, acc[1][1][jj]);
                    acc[2][0][jj] = fma2(ab.x, bb, acc[2][0][jj]);
                    acc[2][1][jj] = fma2(ab.y, bb, acc[2][1][jj]);
                }
            }
        }
        // epilogue for this j-tile
        float inq[4], iq0v[4], iq1v[4];
        #pragma unroll
        for (int jj = 0; jj < 4; ++jj) {
            int cj = b * Ss + j0 + tx * 4 + jj;
            inq[jj]  = g_inv_nq[d][cj];
            iq0v[jj] = g_inv_w2q[d][0][cj];
            iq1v[jj] = g_inv_w2q[d][1][cj];
        }
        float attv[4][4];
        #pragma unroll
        for (int ih = 0; ih < 2; ++ih) {
            #pragma unroll
            for (int jj = 0; jj < 4; ++jj) {
                float x, y;
                upk(acc[0][ih][jj], x, y);
                attv[ih * 2 + 0][jj] = x * inp[ih * 2 + 0] * inq[jj];
                attv[ih * 2 + 1][jj] = y * inp[ih * 2 + 1] * inq[jj];
                upk(acc[1][ih][jj], x, y);
                m2m[0][ih * 2 + 0] = fmaxf(m2m[0][ih * 2 + 0], x * iw0[ih * 2 + 0] * iq0v[jj]);
                m2m[0][ih * 2 + 1] = fmaxf(m2m[0][ih * 2 + 1], y * iw0[ih * 2 + 1] * iq0v[jj]);
                upk(acc[2][ih][jj], x, y);
                m2m[1][ih * 2 + 0] = fmaxf(m2m[1][ih * 2 + 0], x * iw1[ih * 2 + 0] * iq1v[jj]);
                m2m[1][ih * 2 + 1] = fmaxf(m2m[1][ih * 2 + 1], y * iw1[ih * 2 + 1] * iq1v[jj]);
            }
        }
        #pragma unroll
        for (int ii = 0; ii < 4; ++ii) {
            float* attp = &g_att[(b * Ss + i0 + ty * 4 + ii) * Ss + j0 + tx * 4];
            *(float4*)attp = make_float4(attv[ii][0], attv[ii][1], attv[ii][2], attv[ii][3]);
            #pragma unroll
            for (int jj = 0; jj < 4; ++jj) {
                rsum[ii] += attv[ii][jj];
                if (attv[ii][jj] > rmax[ii]) { rmax[ii] = attv[ii][jj]; rarg[ii] = j0 + tx * 4 + jj; }
            }
        }
    }
    // cross-thread (tx-group of 16) reductions
    #pragma unroll
    for (int ii = 0; ii < 4; ++ii) {
        float s = rsum[ii], mx = rmax[ii];
        int ag = rarg[ii];
        float m0 = m2m[0][ii], m1v = m2m[1][ii];
        #pragma unroll
        for (int off = 8; off >= 1; off >>= 1) {
            s += __shfl_xor_sync(0xffffffffu, s, off, 16);
            float omx = __shfl_xor_sync(0xffffffffu, mx, off, 16);
            int   oag = __shfl_xor_sync(0xffffffffu, ag, off, 16);
            if (omx > mx || (omx == mx && oag < ag)) { mx = omx; ag = oag; }
            m0  = fmaxf(m0,  __shfl_xor_sync(0xffffffffu, m0,  off, 16));
            m1v = fmaxf(m1v, __shfl_xor_sync(0xffffffffu, m1v, off, 16));
        }
        if (tx == 0) {
            int i = i0 + ty * 4 + ii;
            int ci = b * Ss + i;
            g_rowinv[d][ci] = 1.0f / s;
            g_idx[d][ci] = ag;
            out[(((2 + d) * Ss + i) * Bb + b) * Ll + 0] = m0;
            out[(((2 + d) * Ss + i) * Bb + b) * Ll + 1] = m1v;
        }
    }
}

// ---------------- 4) hmean GEMM fused with m3 epilogue (one direction) ----------------
__global__ __launch_bounds__(256) void k_hmean(
    const int d, const float* __restrict__ w3f, float* __restrict__ out)
{
    const int b = blockIdx.y, i0 = blockIdx.x * 64;
    const int tid = threadIdx.x, tx = tid & 15, ty = tid >> 4;

    __shared__ __align__(16) float Ats[32 * 68];   // [j][i], stride 68 -> LDS128
    __shared__ ull Qs2[32 * 64];                   // [j][c][16]: conflict-free LDS64
    __shared__ float ws3[2][HP];

    if (tid < HP) {
        float a = (tid < Hh) ? w3f[tid] : 0.0f;
        float c = (tid < Hh) ? w3f[Hh + tid] : 0.0f;
        ws3[0][tid] = a * a;
        ws3[1][tid] = c * c;
    }

    ull hm[4][4];
    #pragma unroll
    for (int ii = 0; ii < 4; ++ii)
        #pragma unroll
        for (int k = 0; k < 4; ++k) hm[ii][k] = 0ull;

    const int h0 = tx * 8;

    for (int j0 = 0; j0 < Ss; j0 += 32) {
        __syncthreads();
        {   // att tile transposed [j][i]
            int j = tid & 31, i2 = tid >> 5;
            #pragma unroll
            for (int r = 0; r < 8; ++r) {
                int i = r * 8 + i2;
                Ats[j * 68 + i] = g_att[(b * Ss + i0 + i) * Ss + j0 + j];
            }
        }
        {   // q tile as packed pairs, interleaved [j][hp&3][hp>>2]
            const ull* srcq = (const ull*)&g_qT[d][(b * Ss + j0) * HP];
            #pragma unroll
            for (int r = 0; r < 8; ++r) {
                int e = r * 256 + tid;
                int j = e >> 6, hp = e & 63;
                Qs2[(j * 4 + (hp & 3)) * 16 + (hp >> 2)] = srcq[j * (HP / 2) + hp];
            }
        }
        __syncthreads();
        #pragma unroll 4
        for (int j = 0; j < 32; ++j) {
            float4 a = *(const float4*)&Ats[j * 68 + ty * 4];
            ull q0 = Qs2[(j * 4 + 0) * 16 + tx];
            ull q1 = Qs2[(j * 4 + 1) * 16 + tx];
            ull q2 = Qs2[(j * 4 + 2) * 16 + tx];
            ull q3 = Qs2[(j * 4 + 3) * 16 + tx];
            ull ap;
            ap = pk(a.x, a.x);
            hm[0][0] = fma2(ap, q0, hm[0][0]); hm[0][1] = fma2(ap, q1, hm[0][1]);
            hm[0][2] = fma2(ap, q2, hm[0][2]); hm[0][3] = fma2(ap, q3, hm[0][3]);
            ap = pk(a.y, a.y);
            hm[1][0] = fma2(ap, q0, hm[1][0]); hm[1][1] = fma2(ap, q1, hm[1][1]);
            hm[1][2] = fma2(ap, q2, hm[1][2]); hm[1][3] = fma2(ap, q3, hm[1][3]);
            ap = pk(a.z, a.z);
            hm[2][0] = fma2(ap, q0, hm[2][0]); hm[2][1] = fma2(ap, q1, hm[2][1]);
            hm[2][2] = fma2(ap, q2, hm[2][2]); hm[2][3] = fma2(ap, q3, hm[2][3]);
            ap = pk(a.w, a.w);
            hm[3][0] = fma2(ap, q0, hm[3][0]); hm[3][1] = fma2(ap, q1, hm[3][1]);
            hm[3][2] = fma2(ap, q2, hm[3][2]); hm[3][3] = fma2(ap, q3, hm[3][3]);
        }
    }

    // m3 epilogue
    #pragma unroll
    for (int ii = 0; ii < 4; ++ii) {
        int i = i0 + ty * 4 + ii;
        int ci = b * Ss + i;
        const float* prow = &g_pT[d][ci * HP + h0];
        float s1a = 0.f, s1b = 0.f, s2a = 0.f, s2b = 0.f;
        #pragma unroll
        for (int k = 0; k < 4; ++k) {
            float hx, hy; upk(hm[ii][k], hx, hy);
            float px = prow[2 * k], py = prow[2 * k + 1];
            float w0x = ws3[0][h0 + 2 * k], w0y = ws3[0][h0 + 2 * k + 1];
            float w1x = ws3[1][h0 + 2 * k], w1y = ws3[1][h0 + 2 * k + 1];
            s1a += w0x * px * hx + w0y * py * hy;
            s2a += w0x * hx * hx + w0y * hy * hy;
            s1b += w1x * px * hx + w1y * py * hy;
            s2b += w1x * hx * hx + w1y * hy * hy;
        }
        #pragma unroll
        for (int off = 8; off >= 1; off >>= 1) {
            s1a += __shfl_xor_sync(0xffffffffu, s1a, off, 16);
            s2a += __shfl_xor_sync(0xffffffffu, s2a, off, 16);
            s1b += __shfl_xor_sync(0xffffffffu, s1b, off, 16);
            s2b += __shfl_xor_sync(0xffffffffu, s2b, off, 16);
        }
        if (tx == 0) {
            float r = g_rowinv[d][ci];
            float ar = fabsf(r);
            float m30 = (r * s1a) * g_inv_w3p[d][0][ci] / fmaxf(ar * sqrtf(s2a), EPSV);
            float m31 = (r * s1b) * g_inv_w3p[d][1][ci] / fmaxf(ar * sqrtf(s2b), EPSV);
            out[(((4 + d) * Ss + i) * Bb + b) * Ll + 0] = m30;
            out[(((4 + d) * Ss + i) * Bb + b) * Ll + 1] = m31;
        }
    }
}

// ---------------- 5) m1 + m4 ----------------
__global__ __launch_bounds__(256) void k_m14(
    const float* __restrict__ w1f, const float* __restrict__ w1b,
    const float* __restrict__ w4f, float* __restrict__ out)
{
    const int d = blockIdx.y;
    const int c = blockIdx.x * 8 + (threadIdx.x >> 5);
    const int lane = threadIdx.x & 31;
    const int b = c / Ss, i = c % Ss;
    const int jm = g_idx[d][c];

    const float* prow = g_pT[d] + c * HP;
    const float* ql = g_qT[d] + (b * Ss + Ss - 1) * HP;
    const float* qm = g_qT[d] + (b * Ss + jm) * HP;
    const float* wa1 = d ? w1b : w1f;

    float s1[2] = {0.f, 0.f}, s4[2] = {0.f, 0.f};
    for (int h = lane; h < Hh; h += 32) {
        float p = prow[h];
        float t1 = p * ql[h];
        float t4 = p * qm[h];
        #pragma unroll
        for (int l = 0; l < 2; ++l) {
            float a;
            a = wa1[l * Hh + h]; s1[l] += a * a * t1;
            a = w4f[l * Hh + h]; s4[l] += a * a * t4;
        }
    }
    #pragma unroll
    for (int l = 0; l < 2; ++l) { s1[l] = wred(s1[l]); s4[l] = wred(s4[l]); }
    if (lane == 0) {
        #pragma unroll
        for (int l = 0; l < 2; ++l) {
            out[(((0 + d) * Ss + i) * Bb + b) * Ll + l] =
                s1[l] * g_inv_w1p[d][l][c] * g_inv_w1ql[d][l][b];
            out[(((6 + d) * Ss + i) * Bb + b) * Ll + l] =
                s4[l] * g_inv_w4p[d][l][c] * g_inv_w4q[d][l][b * Ss + jm];
        }
    }
}

// ---------------- launch ----------------
extern "C" void kernel_launch(void* const* d_in, const int* in_sizes, int n_in,
                              void* d_out, int out_size) {
    const float* p_f = (const float*)d_in[0];
    const float* p_b = (const float*)d_in[1];
    const float* q_f = (const float*)d_in[2];
    const float* q_b = (const float*)d_in[3];
    const float* w1f = (const float*)d_in[4];
    const float* w1b = (const float*)d_in[5];
    const float* w2f = (const float*)d_in[6];
    const float* w2b = (const float*)d_in[7];
    const float* w3f = (const float*)d_in[8];
    // w3b (d_in[9]) intentionally unused: reference uses w3f/w4f for both directions
    const float* w4f = (const float*)d_in[10];
    float* out = (float*)d_out;

    cudaFuncSetAttribute(k_cross, cudaFuncAttributeMaxDynamicSharedMemorySize,
                         CROSS_SMEM_BYTES);

    k_transpose<<<dim3(Ss / 64, Bb, 4), 256>>>(p_f, p_b, q_f, q_b);
    k_norms<<<dim3((Bb * Ss) / 8, 2, 2), 256>>>(w1f, w1b, w2f, w2b, w3f, w4f);
    for (int d = 0; d < 2; ++d) {
        k_cross<<<dim3(Ss / 64, Bb), 256, CROSS_SMEM_BYTES>>>(d, w2f, w2b, out);
        k_hmean<<<dim3(Ss / 64, Bb), 256>>>(d, w3f, out);
    }
    k_m14<<<dim3((Bb * Ss) / 8, 2), 256>>>(w1f, w1b, w4f, out);
}